// round 5
// baseline (speedup 1.0000x reference)
#include <cuda_runtime.h>
#include <cuda_bf16.h>
#include <cstdint>

// Problem constants
#define B_    64
#define T_    1000
#define INF   512
#define OUTF  512

// Scratch (static __device__ allocations are allowed)
__device__ float         g_cur[(size_t)B_ * T_ * OUTF];
__device__ __nv_bfloat16 g_xh[(size_t)B_ * T_ * INF];
__device__ __nv_bfloat16 g_xl[(size_t)B_ * T_ * INF];
__device__ __nv_bfloat16 g_wh[(size_t)OUTF * INF];
__device__ __nv_bfloat16 g_wl[(size_t)OUTF * INF];

// ---------------------------------------------------------------------------
// PTX helpers (target-generic: ldmatrix / mma.sync / cp.async only)
// ---------------------------------------------------------------------------
__device__ __forceinline__ uint32_t smem_u32(const void* p) {
    uint32_t a;
    asm("{ .reg .u64 t; cvta.to.shared.u64 t, %1; cvt.u32.u64 %0, t; }"
        : "=r"(a) : "l"(p));
    return a;
}

__device__ __forceinline__ void ldsm_x4(uint32_t* r, uint32_t addr) {
    asm volatile("ldmatrix.sync.aligned.m8n8.x4.shared.b16 {%0,%1,%2,%3}, [%4];"
                 : "=r"(r[0]), "=r"(r[1]), "=r"(r[2]), "=r"(r[3]) : "r"(addr));
}

__device__ __forceinline__ void mma16816(float* d, const uint32_t* a,
                                         const uint32_t* b) {
    asm volatile(
        "mma.sync.aligned.m16n8k16.row.col.f32.bf16.bf16.f32 "
        "{%0,%1,%2,%3}, {%4,%5,%6,%7}, {%8,%9}, {%0,%1,%2,%3};"
        : "+f"(d[0]), "+f"(d[1]), "+f"(d[2]), "+f"(d[3])
        : "r"(a[0]), "r"(a[1]), "r"(a[2]), "r"(a[3]), "r"(b[0]), "r"(b[1]));
}

#define CP_ASYNC16(dst, src)                                                  \
    asm volatile("cp.async.cg.shared.global [%0], [%1], 16;" :: "r"(dst), "l"(src))
#define CP_COMMIT() asm volatile("cp.async.commit_group;" ::: "memory")
#define CP_WAIT1()  asm volatile("cp.async.wait_group 1;" ::: "memory")

// ---------------------------------------------------------------------------
// Stage 0: fp32 -> (bf16 hi, bf16 lo) split
// ---------------------------------------------------------------------------
__global__ void split_kernel(const float* __restrict__ src,
                             __nv_bfloat16* __restrict__ hi,
                             __nv_bfloat16* __restrict__ lo, int n4)
{
    int i = blockIdx.x * blockDim.x + threadIdx.x;
    if (i >= n4) return;
    float4 v = ((const float4*)src)[i];
    __nv_bfloat16 h0 = __float2bfloat16_rn(v.x);
    __nv_bfloat16 h1 = __float2bfloat16_rn(v.y);
    __nv_bfloat16 h2 = __float2bfloat16_rn(v.z);
    __nv_bfloat16 h3 = __float2bfloat16_rn(v.w);
    __nv_bfloat16 l0 = __float2bfloat16_rn(v.x - __bfloat162float(h0));
    __nv_bfloat16 l1 = __float2bfloat16_rn(v.y - __bfloat162float(h1));
    __nv_bfloat16 l2 = __float2bfloat16_rn(v.z - __bfloat162float(h2));
    __nv_bfloat16 l3 = __float2bfloat16_rn(v.w - __bfloat162float(h3));
    uint2 hv, lv;
    hv.x = (uint32_t)__bfloat16_as_ushort(h0) | ((uint32_t)__bfloat16_as_ushort(h1) << 16);
    hv.y = (uint32_t)__bfloat16_as_ushort(h2) | ((uint32_t)__bfloat16_as_ushort(h3) << 16);
    lv.x = (uint32_t)__bfloat16_as_ushort(l0) | ((uint32_t)__bfloat16_as_ushort(l1) << 16);
    lv.y = (uint32_t)__bfloat16_as_ushort(l2) | ((uint32_t)__bfloat16_as_ushort(l3) << 16);
    ((uint2*)hi)[i] = hv;
    ((uint2*)lo)[i] = lv;
}

// ---------------------------------------------------------------------------
// Stage 1: HMMA bf16-split GEMM (grid transposed for L2 reuse of A tiles)
// ---------------------------------------------------------------------------
#define BM 128
#define BN 128
#define BK 32
#define NSTAGE 3
#define ROWB 80
#define STAGE_BYTES (4 * BM * ROWB)
#define OFF_AH 0
#define OFF_AL (BM * ROWB)
#define OFF_BH (2 * BM * ROWB)
#define OFF_BL (3 * BM * ROWB)
#define SM_TOT (NSTAGE * STAGE_BYTES)

__global__ __launch_bounds__(256, 1) void gemm_hmma_kernel(
    const __nv_bfloat16* __restrict__ xh, const __nv_bfloat16* __restrict__ xl,
    const __nv_bfloat16* __restrict__ wh, const __nv_bfloat16* __restrict__ wl,
    float* __restrict__ C)
{
    extern __shared__ char smem[];
    const uint32_t sb = smem_u32(smem);
    const int tid  = threadIdx.x;
    const int wid  = tid >> 5;
    const int lane = tid & 31;
    const int bm = blockIdx.y * BM;   // transposed: y = M blocks (500)
    const int bn = blockIdx.x * BN;   //             x = N blocks (4)
    const int wm = (wid >> 2) * 64;
    const int wn = (wid & 3) * 32;

    const int r0 = tid >> 2;
    const int c0 = tid & 3;
    const int r1 = (tid + 256) >> 2;
    const int c1 = c0;

    float acc[4][4][4];
#pragma unroll
    for (int i = 0; i < 4; ++i)
#pragma unroll
        for (int j = 0; j < 4; ++j)
#pragma unroll
            for (int k = 0; k < 4; ++k) acc[i][j][k] = 0.f;

    const int a_row = (lane & 15);
    const int a_cb  = (lane >> 4) * 16;
    const int b_g   = lane >> 3;
    const int b_row = ((b_g & 2) ? 8 : 0) + (lane & 7);
    const int b_cb  = (b_g & 1) * 16;

#define LOAD_STAGE(st, kt)                                                    \
    do {                                                                      \
        const int koff = (kt) * BK;                                           \
        uint32_t base = sb + (st) * STAGE_BYTES;                              \
        CP_ASYNC16(base + OFF_AH + r0 * ROWB + c0 * 16,                       \
                   xh + (size_t)(bm + r0) * INF + koff + c0 * 8);             \
        CP_ASYNC16(base + OFF_AH + r1 * ROWB + c1 * 16,                       \
                   xh + (size_t)(bm + r1) * INF + koff + c1 * 8);             \
        CP_ASYNC16(base + OFF_AL + r0 * ROWB + c0 * 16,                       \
                   xl + (size_t)(bm + r0) * INF + koff + c0 * 8);             \
        CP_ASYNC16(base + OFF_AL + r1 * ROWB + c1 * 16,                       \
                   xl + (size_t)(bm + r1) * INF + koff + c1 * 8);             \
        CP_ASYNC16(base + OFF_BH + r0 * ROWB + c0 * 16,                       \
                   wh + (size_t)(bn + r0) * INF + koff + c0 * 8);             \
        CP_ASYNC16(base + OFF_BH + r1 * ROWB + c1 * 16,                       \
                   wh + (size_t)(bn + r1) * INF + koff + c1 * 8);             \
        CP_ASYNC16(base + OFF_BL + r0 * ROWB + c0 * 16,                       \
                   wl + (size_t)(bn + r0) * INF + koff + c0 * 8);             \
        CP_ASYNC16(base + OFF_BL + r1 * ROWB + c1 * 16,                       \
                   wl + (size_t)(bn + r1) * INF + koff + c1 * 8);             \
    } while (0)

    LOAD_STAGE(0, 0);
    CP_COMMIT();
    LOAD_STAGE(1, 1);
    CP_COMMIT();

    const int KT = INF / BK;
    for (int kt = 0; kt < KT; ++kt) {
        const int st = kt % NSTAGE;
        CP_WAIT1();
        __syncthreads();

        if (kt + 2 < KT) LOAD_STAGE((kt + 2) % NSTAGE, kt + 2);
        CP_COMMIT();

        const uint32_t base = sb + st * STAGE_BYTES;
#pragma unroll
        for (int ks = 0; ks < 2; ++ks) {
            uint32_t ah[4][4], al[4][4], bh[4][2], bl[4][2];
#pragma unroll
            for (int mi = 0; mi < 4; ++mi) {
                uint32_t ra = base + OFF_AH +
                              (uint32_t)(wm + mi * 16 + a_row) * ROWB +
                              ks * 32 + a_cb;
                ldsm_x4(ah[mi], ra);
                ldsm_x4(al[mi], ra + (OFF_AL - OFF_AH));
            }
#pragma unroll
            for (int nj = 0; nj < 2; ++nj) {
                uint32_t rb = base + OFF_BH +
                              (uint32_t)(wn + nj * 16 + b_row) * ROWB +
                              ks * 32 + b_cb;
                uint32_t t[4];
                ldsm_x4(t, rb);
                bh[2 * nj][0] = t[0]; bh[2 * nj][1] = t[1];
                bh[2 * nj + 1][0] = t[2]; bh[2 * nj + 1][1] = t[3];
                ldsm_x4(t, rb + (OFF_BL - OFF_BH));
                bl[2 * nj][0] = t[0]; bl[2 * nj][1] = t[1];
                bl[2 * nj + 1][0] = t[2]; bl[2 * nj + 1][1] = t[3];
            }
#pragma unroll
            for (int mi = 0; mi < 4; ++mi)
#pragma unroll
                for (int ni = 0; ni < 4; ++ni) {
                    mma16816(acc[mi][ni], ah[mi], bh[ni]);
                    mma16816(acc[mi][ni], ah[mi], bl[ni]);
                    mma16816(acc[mi][ni], al[mi], bh[ni]);
                }
        }
    }

    const int er = lane >> 2;
    const int ec = (lane & 3) * 2;
#pragma unroll
    for (int mi = 0; mi < 4; ++mi) {
#pragma unroll
        for (int ni = 0; ni < 4; ++ni) {
            size_t row0 = (size_t)(bm + wm + mi * 16 + er);
            size_t col  = (size_t)(bn + wn + ni * 8 + ec);
            float2 v0 = make_float2(acc[mi][ni][0], acc[mi][ni][1]);
            float2 v1 = make_float2(acc[mi][ni][2], acc[mi][ni][3]);
            *(float2*)&C[row0 * OUTF + col]       = v0;
            *(float2*)&C[(row0 + 8) * OUTF + col] = v1;
        }
    }
}

// ---------------------------------------------------------------------------
// Stage 2: ALIF scan with producer/writer warp specialization.
// 1024 thr/CTA: tid<512 compute the recurrence, tid>=512 drain a double-
// buffered smem staging area to gmem with one STG.128 per thread per step.
// ---------------------------------------------------------------------------
__global__ __launch_bounds__(1024, 1) void alif_scan_kernel(
    const float* __restrict__ cur_in,
    const float* __restrict__ bias,
    const float* __restrict__ R,
    const float* __restrict__ beta,
    const float* __restrict__ beta2,
    const float* __restrict__ decay_v,
    const float* __restrict__ decay_b,
    float* __restrict__ out)
{
    const int b   = blockIdx.x;
    const int tid = threadIdx.x;
    const bool prod = tid < OUTF;
    const int o = tid & (OUTF - 1);

    __shared__ __align__(16) float zsm[OUTF];
    __shared__ __align__(16) float bufv[2][OUTF];
    __shared__ __align__(16) float bufz[2][OUTF];
    __shared__ __align__(16) float bufb[2][OUTF];

    const size_t SB = (size_t)B_ * T_ * OUTF;

    // zero the t=0 pads (3 state tensors)
    for (int idx = tid; idx < 3 * OUTF; idx += 1024) {
        int st = idx >> 9;
        int oo = idx & (OUTF - 1);
        out[SB + (((size_t)st * B_ + b) * (T_ + 1)) * OUTF + oo] = 0.f;
    }

    // producer state & params
    float Bias = 0.f, Beta = 0.f, Beta2 = 0.f, Dv = 0.f, Db = 0.f;
    const float* cin = nullptr;
    if (prod) {
        Bias = bias[o]; Beta = beta[o]; Beta2 = beta2[o];
        Dv = decay_v[o]; Db = decay_b[o];
        cin = cur_in + ((size_t)b * T_) * OUTF + o;
    }
    const float omDv = 1.f - Dv;
    const float omDb = 1.f - Db;
    float v = 0.f, z = 0.f, ba = 0.f;

    // writer stream setup: s=0 -> zs(z), 1 -> vs(v), 2 -> z_full(z), 3 -> b_full(b)
    const int ws = (tid - OUTF) >> 7;        // 0..3
    const int wq = (tid & 127) * 4;          // 0..508 step 4
    float* wbase = nullptr;
    if (!prod) {
        if (ws == 0)
            wbase = out + ((size_t)b * T_) * OUTF + wq;
        else {
            int st = ws - 1;                 // 0:v 1:z 2:b  -> tensors 0,1,2
            // map ws=1->state0(v), ws=2->state1(z), ws=3->state2(b)
            wbase = out + SB + (((size_t)st * B_ + b) * (T_ + 1) + 1) * OUTF + wq;
        }
    }

    float p[8];
    if (prod) {
#pragma unroll
        for (int j = 0; j < 8; ++j) p[j] = cin[(size_t)j * OUTF];
    }

    for (int t = 0; t < T_; t += 8) {
        float n[8];
        if (prod) {
            if (t + 8 < T_) {
#pragma unroll
                for (int j = 0; j < 8; ++j) n[j] = cin[(size_t)(t + 8 + j) * OUTF];
            } else {
#pragma unroll
                for (int j = 0; j < 8; ++j) n[j] = 0.f;
            }
        }
#pragma unroll
        for (int j = 0; j < 8; ++j) {
            const int tt = t + j;
            if (prod) zsm[o] = z;
            int cnt = __syncthreads_count(prod && z != 0.f);
            float rec = 0.f;
            if (cnt) {                        // uniform across block
                if (prod) {
                    for (int jj = 0; jj < OUTF; ++jj) {
                        float zj = zsm[jj];
                        if (zj != 0.f) rec += R[(size_t)o * OUTF + jj];
                    }
                }
                __syncthreads();
            }
            if (prod) {
                v *= (1.f - z);
                float c = p[j] + Bias + rec;
                v = Dv * v + omDv * (c - ba);
                z = (v >= 1.0f) ? 1.f : 0.f;
                ba = Db * ba + omDb * (Beta * v + Beta2 * z);
                const int slot = tt & 1;
                bufv[slot][o] = v;
                bufz[slot][o] = z;
                bufb[slot][o] = ba;
            } else if (tt > 0) {
                const int slot = (tt - 1) & 1;
                float4 val;
                if (ws == 0 || ws == 2) val = *(const float4*)&bufz[slot][wq];
                else if (ws == 1)       val = *(const float4*)&bufv[slot][wq];
                else                    val = *(const float4*)&bufb[slot][wq];
                *(float4*)&wbase[(size_t)(tt - 1) * OUTF] = val;
            }
        }
        if (prod) {
#pragma unroll
            for (int j = 0; j < 8; ++j) p[j] = n[j];
        }
    }
    __syncthreads();
    if (!prod) {
        const int slot = (T_ - 1) & 1;
        float4 val;
        if (ws == 0 || ws == 2) val = *(const float4*)&bufz[slot][wq];
        else if (ws == 1)       val = *(const float4*)&bufv[slot][wq];
        else                    val = *(const float4*)&bufb[slot][wq];
        *(float4*)&wbase[(size_t)(T_ - 1) * OUTF] = val;
    }
}

// ---------------------------------------------------------------------------
// Launch
// ---------------------------------------------------------------------------
extern "C" void kernel_launch(void* const* d_in, const int* in_sizes, int n_in,
                              void* d_out, int out_size)
{
    const float* x     = (const float*)d_in[0];
    const float* w     = (const float*)d_in[1];
    const float* bias  = (const float*)d_in[2];
    const float* R     = (const float*)d_in[3];
    const float* beta  = (const float*)d_in[4];
    const float* beta2 = (const float*)d_in[5];
    const float* dv    = (const float*)d_in[6];
    const float* db    = (const float*)d_in[7];
    float* out = (float*)d_out;

    float* cur = nullptr;
    __nv_bfloat16 *xh, *xl, *wh, *wl;
    cudaGetSymbolAddress((void**)&cur, g_cur);
    cudaGetSymbolAddress((void**)&xh, g_xh);
    cudaGetSymbolAddress((void**)&xl, g_xl);
    cudaGetSymbolAddress((void**)&wh, g_wh);
    cudaGetSymbolAddress((void**)&wl, g_wl);

    cudaFuncSetAttribute(gemm_hmma_kernel,
                         cudaFuncAttributeMaxDynamicSharedMemorySize, SM_TOT);

    const int n4x = (B_ * T_ * INF) / 4;
    const int n4w = (OUTF * INF) / 4;
    split_kernel<<<(n4x + 255) / 256, 256>>>(x, xh, xl, n4x);
    split_kernel<<<(n4w + 255) / 256, 256>>>(w, wh, wl, n4w);

    dim3 grid(OUTF / BN, (B_ * T_) / BM);   // (4, 500): A-tile sharers adjacent
    gemm_hmma_kernel<<<grid, 256, SM_TOT>>>(xh, xl, wh, wl, cur);
    alif_scan_kernel<<<B_, 1024>>>(cur, bias, R, beta, beta2, dv, db, out);
}

// round 6
// speedup vs baseline: 1.3724x; 1.3724x over previous
#include <cuda_runtime.h>
#include <cuda_fp16.h>
#include <cstdint>

// Problem constants
#define B_    64
#define T_    1000
#define INF   512
#define OUTF  512

// Scratch (static __device__ allocations are allowed)
__device__ float  g_cur[(size_t)B_ * T_ * OUTF];
__device__ __half g_xh[(size_t)B_ * T_ * INF];
__device__ __half g_wh[(size_t)OUTF * INF];
__device__ __half g_wl[(size_t)OUTF * INF];

// ---------------------------------------------------------------------------
// PTX helpers (target-generic: ldmatrix / mma.sync / cp.async only)
// ---------------------------------------------------------------------------
__device__ __forceinline__ uint32_t smem_u32(const void* p) {
    uint32_t a;
    asm("{ .reg .u64 t; cvta.to.shared.u64 t, %1; cvt.u32.u64 %0, t; }"
        : "=r"(a) : "l"(p));
    return a;
}

__device__ __forceinline__ void ldsm_x4(uint32_t* r, uint32_t addr) {
    asm volatile("ldmatrix.sync.aligned.m8n8.x4.shared.b16 {%0,%1,%2,%3}, [%4];"
                 : "=r"(r[0]), "=r"(r[1]), "=r"(r[2]), "=r"(r[3]) : "r"(addr));
}

__device__ __forceinline__ void mma16816(float* d, const uint32_t* a,
                                         const uint32_t* b) {
    asm volatile(
        "mma.sync.aligned.m16n8k16.row.col.f32.f16.f16.f32 "
        "{%0,%1,%2,%3}, {%4,%5,%6,%7}, {%8,%9}, {%0,%1,%2,%3};"
        : "+f"(d[0]), "+f"(d[1]), "+f"(d[2]), "+f"(d[3])
        : "r"(a[0]), "r"(a[1]), "r"(a[2]), "r"(a[3]), "r"(b[0]), "r"(b[1]));
}

#define CP_ASYNC16(dst, src)                                                  \
    asm volatile("cp.async.cg.shared.global [%0], [%1], 16;" :: "r"(dst), "l"(src))
#define CP_COMMIT() asm volatile("cp.async.commit_group;" ::: "memory")
#define CP_WAIT1()  asm volatile("cp.async.wait_group 1;" ::: "memory")

// ---------------------------------------------------------------------------
// Stage 0a: fp32 -> fp16 hi only (for x)
// ---------------------------------------------------------------------------
__global__ void split_hi_kernel(const float* __restrict__ src,
                                __half* __restrict__ hi, int n4)
{
    int i = blockIdx.x * blockDim.x + threadIdx.x;
    if (i >= n4) return;
    float4 v = ((const float4*)src)[i];
    __half h0 = __float2half_rn(v.x);
    __half h1 = __float2half_rn(v.y);
    __half h2 = __float2half_rn(v.z);
    __half h3 = __float2half_rn(v.w);
    uint2 hv;
    hv.x = (uint32_t)__half_as_ushort(h0) | ((uint32_t)__half_as_ushort(h1) << 16);
    hv.y = (uint32_t)__half_as_ushort(h2) | ((uint32_t)__half_as_ushort(h3) << 16);
    ((uint2*)hi)[i] = hv;
}

// Stage 0b: fp32 -> (fp16 hi, fp16 lo) split (for W)
__global__ void split_hilo_kernel(const float* __restrict__ src,
                                  __half* __restrict__ hi,
                                  __half* __restrict__ lo, int n4)
{
    int i = blockIdx.x * blockDim.x + threadIdx.x;
    if (i >= n4) return;
    float4 v = ((const float4*)src)[i];
    __half h0 = __float2half_rn(v.x);
    __half h1 = __float2half_rn(v.y);
    __half h2 = __float2half_rn(v.z);
    __half h3 = __float2half_rn(v.w);
    __half l0 = __float2half_rn(v.x - __half2float(h0));
    __half l1 = __float2half_rn(v.y - __half2float(h1));
    __half l2 = __float2half_rn(v.z - __half2float(h2));
    __half l3 = __float2half_rn(v.w - __half2float(h3));
    uint2 hv, lv;
    hv.x = (uint32_t)__half_as_ushort(h0) | ((uint32_t)__half_as_ushort(h1) << 16);
    hv.y = (uint32_t)__half_as_ushort(h2) | ((uint32_t)__half_as_ushort(h3) << 16);
    lv.x = (uint32_t)__half_as_ushort(l0) | ((uint32_t)__half_as_ushort(l1) << 16);
    lv.y = (uint32_t)__half_as_ushort(l2) | ((uint32_t)__half_as_ushort(l3) << 16);
    ((uint2*)hi)[i] = hv;
    ((uint2*)lo)[i] = lv;
}

// ---------------------------------------------------------------------------
// Stage 1: HMMA fp16 2-pass GEMM.  C = xh*(wh)^T + xh*(wl)^T
// BM=128 BN=128 BK=32, 256 thr, 3-stage cp.async, padded 80B rows.
// ---------------------------------------------------------------------------
#define BM 128
#define BN 128
#define BK 32
#define NSTAGE 3
#define ROWB 80
#define STAGE_BYTES (3 * BM * ROWB)   // A, Bh, Bl: 30720
#define OFF_A  0
#define OFF_BH (BM * ROWB)
#define OFF_BL (2 * BM * ROWB)
#define SM_TOT (NSTAGE * STAGE_BYTES) // 92160

__global__ __launch_bounds__(256, 1) void gemm_hmma_kernel(
    const __half* __restrict__ xh,
    const __half* __restrict__ wh, const __half* __restrict__ wl,
    float* __restrict__ C)
{
    extern __shared__ char smem[];
    const uint32_t sb = smem_u32(smem);
    const int tid  = threadIdx.x;
    const int wid  = tid >> 5;
    const int lane = tid & 31;
    const int bm = blockIdx.y * BM;
    const int bn = blockIdx.x * BN;
    const int wm = (wid >> 2) * 64;
    const int wn = (wid & 3) * 32;

    const int r0 = tid >> 2;
    const int c0 = tid & 3;
    const int r1 = (tid + 256) >> 2;

    float acc[4][4][4];
#pragma unroll
    for (int i = 0; i < 4; ++i)
#pragma unroll
        for (int j = 0; j < 4; ++j)
#pragma unroll
            for (int k = 0; k < 4; ++k) acc[i][j][k] = 0.f;

    const int a_row = (lane & 15);
    const int a_cb  = (lane >> 4) * 16;
    const int b_g   = lane >> 3;
    const int b_row = ((b_g & 2) ? 8 : 0) + (lane & 7);
    const int b_cb  = (b_g & 1) * 16;

#define LOAD_STAGE(st, kt)                                                    \
    do {                                                                      \
        const int koff = (kt) * BK;                                           \
        uint32_t base = sb + (st) * STAGE_BYTES;                              \
        CP_ASYNC16(base + OFF_A + r0 * ROWB + c0 * 16,                        \
                   xh + (size_t)(bm + r0) * INF + koff + c0 * 8);             \
        CP_ASYNC16(base + OFF_A + r1 * ROWB + c0 * 16,                        \
                   xh + (size_t)(bm + r1) * INF + koff + c0 * 8);             \
        CP_ASYNC16(base + OFF_BH + r0 * ROWB + c0 * 16,                       \
                   wh + (size_t)(bn + r0) * INF + koff + c0 * 8);             \
        CP_ASYNC16(base + OFF_BH + r1 * ROWB + c0 * 16,                       \
                   wh + (size_t)(bn + r1) * INF + koff + c0 * 8);             \
        CP_ASYNC16(base + OFF_BL + r0 * ROWB + c0 * 16,                       \
                   wl + (size_t)(bn + r0) * INF + koff + c0 * 8);             \
        CP_ASYNC16(base + OFF_BL + r1 * ROWB + c0 * 16,                       \
                   wl + (size_t)(bn + r1) * INF + koff + c0 * 8);             \
    } while (0)

    LOAD_STAGE(0, 0);
    CP_COMMIT();
    LOAD_STAGE(1, 1);
    CP_COMMIT();

    const int KT = INF / BK;
    for (int kt = 0; kt < KT; ++kt) {
        const int st = kt % NSTAGE;
        CP_WAIT1();
        __syncthreads();

        if (kt + 2 < KT) LOAD_STAGE((kt + 2) % NSTAGE, kt + 2);
        CP_COMMIT();

        const uint32_t base = sb + st * STAGE_BYTES;
#pragma unroll
        for (int ks = 0; ks < 2; ++ks) {
            uint32_t ah[4][4], bh[4][2], bl[4][2];
#pragma unroll
            for (int mi = 0; mi < 4; ++mi) {
                uint32_t ra = base + OFF_A +
                              (uint32_t)(wm + mi * 16 + a_row) * ROWB +
                              ks * 32 + a_cb;
                ldsm_x4(ah[mi], ra);
            }
#pragma unroll
            for (int nj = 0; nj < 2; ++nj) {
                uint32_t rb = base + OFF_BH +
                              (uint32_t)(wn + nj * 16 + b_row) * ROWB +
                              ks * 32 + b_cb;
                uint32_t t[4];
                ldsm_x4(t, rb);
                bh[2 * nj][0] = t[0]; bh[2 * nj][1] = t[1];
                bh[2 * nj + 1][0] = t[2]; bh[2 * nj + 1][1] = t[3];
                ldsm_x4(t, rb + (OFF_BL - OFF_BH));
                bl[2 * nj][0] = t[0]; bl[2 * nj][1] = t[1];
                bl[2 * nj + 1][0] = t[2]; bl[2 * nj + 1][1] = t[3];
            }
#pragma unroll
            for (int mi = 0; mi < 4; ++mi)
#pragma unroll
                for (int ni = 0; ni < 4; ++ni) {
                    mma16816(acc[mi][ni], ah[mi], bh[ni]);
                    mma16816(acc[mi][ni], ah[mi], bl[ni]);
                }
        }
    }

    const int er = lane >> 2;
    const int ec = (lane & 3) * 2;
#pragma unroll
    for (int mi = 0; mi < 4; ++mi) {
#pragma unroll
        for (int ni = 0; ni < 4; ++ni) {
            size_t row0 = (size_t)(bm + wm + mi * 16 + er);
            size_t col  = (size_t)(bn + wn + ni * 8 + ec);
            float2 v0 = make_float2(acc[mi][ni][0], acc[mi][ni][1]);
            float2 v1 = make_float2(acc[mi][ni][2], acc[mi][ni][3]);
            *(float2*)&C[row0 * OUTF + col]       = v0;
            *(float2*)&C[(row0 + 8) * OUTF + col] = v1;
        }
    }
}

// ---------------------------------------------------------------------------
// Stage 2: speculative windowed ALIF scan; 2 CTAs per batch split the stores.
// Window K=8: 2 barriers/window fast path; exact per-step redo on any spike.
// ---------------------------------------------------------------------------
__global__ __launch_bounds__(512, 1) void alif_scan_kernel(
    const float* __restrict__ cur_in,
    const float* __restrict__ bias,
    const float* __restrict__ R,
    const float* __restrict__ beta,
    const float* __restrict__ beta2,
    const float* __restrict__ decay_v,
    const float* __restrict__ decay_b,
    float* __restrict__ out)
{
    const int b    = blockIdx.x >> 1;
    const int role = blockIdx.x & 1;
    const int o    = threadIdx.x;

    __shared__ float zsm[OUTF];

    const float Bias  = bias[o];
    const float Beta  = beta[o];
    const float Beta2 = beta2[o];
    const float Dv    = decay_v[o];
    const float Db    = decay_b[o];
    const float omDv  = 1.f - Dv;
    const float omDb  = 1.f - Db;

    float v = 0.f, z = 0.f, ba = 0.f;

    const size_t SB = (size_t)B_ * T_ * OUTF;
    float* s0 = out + ((size_t)b * T_) * OUTF + o;                               // zs
    float* s1 = out + SB + (((size_t)0 * B_ + b) * (T_ + 1) + 1) * OUTF + o;     // v_full
    float* s2 = out + SB + (((size_t)1 * B_ + b) * (T_ + 1) + 1) * OUTF + o;     // z_full
    float* s3 = out + SB + (((size_t)2 * B_ + b) * (T_ + 1) + 1) * OUTF + o;     // b_full

    // zero t=0 pads: role 0 -> state0; role 1 -> state1, state2
    if (role == 0) {
        out[SB + (((size_t)0 * B_ + b) * (T_ + 1)) * OUTF + o] = 0.f;
    } else {
        out[SB + (((size_t)1 * B_ + b) * (T_ + 1)) * OUTF + o] = 0.f;
        out[SB + (((size_t)2 * B_ + b) * (T_ + 1)) * OUTF + o] = 0.f;
    }

    const float* cin = cur_in + ((size_t)b * T_) * OUTF + o;

    float p[8];
#pragma unroll
    for (int j = 0; j < 8; ++j) p[j] = cin[(size_t)j * OUTF];

    for (int t = 0; t < T_; t += 8) {
        // prefetch next window (MLP=8)
        float n[8];
        if (t + 8 < T_) {
#pragma unroll
            for (int j = 0; j < 8; ++j) n[j] = cin[(size_t)(t + 8 + j) * OUTF];
        } else {
#pragma unroll
            for (int j = 0; j < 8; ++j) n[j] = 0.f;
        }

        // entry-spike check (feeds rec at step 0 of the window)
        zsm[o] = z;
        int cnt = __syncthreads_count(z != 0.f);
        float rec0 = 0.f;
        if (cnt) {
            for (int jj = 0; jj < OUTF; ++jj)
                if (zsm[jj] != 0.f) rec0 += R[(size_t)o * OUTF + jj];
        }

        // speculative local run: rec = 0 for steps 1..7
        float sv = v, sz = z, sb2 = ba;
        float ov[8], oz[8], ob[8];
        bool any = false;
#pragma unroll
        for (int j = 0; j < 8; ++j) {
            float rec = (j == 0) ? rec0 : 0.f;
            v *= (1.f - z);
            float c = p[j] + Bias + rec;
            v = Dv * v + omDv * (c - ba);
            z = (v >= 1.0f) ? 1.f : 0.f;
            ba = Db * ba + omDb * (Beta * v + Beta2 * z);
            ov[j] = v; oz[j] = z; ob[j] = ba;
            if (j < 7) any |= (z != 0.f);
        }
        int cnt2 = __syncthreads_count(any);
        if (cnt2) {
            // rollback + exact per-step redo
            v = sv; z = sz; ba = sb2;
            for (int j = 0; j < 8; ++j) {
                zsm[o] = z;
                int c3 = __syncthreads_count(z != 0.f);
                float rec = 0.f;
                if (c3) {
                    for (int jj = 0; jj < OUTF; ++jj)
                        if (zsm[jj] != 0.f) rec += R[(size_t)o * OUTF + jj];
                }
                v *= (1.f - z);
                float c = p[j] + Bias + rec;
                v = Dv * v + omDv * (c - ba);
                z = (v >= 1.0f) ? 1.f : 0.f;
                ba = Db * ba + omDb * (Beta * v + Beta2 * z);
                ov[j] = v; oz[j] = z; ob[j] = ba;
                __syncthreads();   // protect zsm before next overwrite
            }
        }

        // stores: role 0 -> zs + v_full; role 1 -> z_full + b_full
        if (role == 0) {
#pragma unroll
            for (int j = 0; j < 8; ++j) s0[(size_t)(t + j) * OUTF] = oz[j];
#pragma unroll
            for (int j = 0; j < 8; ++j) s1[(size_t)(t + j) * OUTF] = ov[j];
        } else {
#pragma unroll
            for (int j = 0; j < 8; ++j) s2[(size_t)(t + j) * OUTF] = oz[j];
#pragma unroll
            for (int j = 0; j < 8; ++j) s3[(size_t)(t + j) * OUTF] = ob[j];
        }

#pragma unroll
        for (int j = 0; j < 8; ++j) p[j] = n[j];
    }
}

// ---------------------------------------------------------------------------
// Launch
// ---------------------------------------------------------------------------
extern "C" void kernel_launch(void* const* d_in, const int* in_sizes, int n_in,
                              void* d_out, int out_size)
{
    const float* x     = (const float*)d_in[0];
    const float* w     = (const float*)d_in[1];
    const float* bias  = (const float*)d_in[2];
    const float* R     = (const float*)d_in[3];
    const float* beta  = (const float*)d_in[4];
    const float* beta2 = (const float*)d_in[5];
    const float* dv    = (const float*)d_in[6];
    const float* db    = (const float*)d_in[7];
    float* out = (float*)d_out;

    float* cur = nullptr;
    __half *xh, *wh, *wl;
    cudaGetSymbolAddress((void**)&cur, g_cur);
    cudaGetSymbolAddress((void**)&xh, g_xh);
    cudaGetSymbolAddress((void**)&wh, g_wh);
    cudaGetSymbolAddress((void**)&wl, g_wl);

    cudaFuncSetAttribute(gemm_hmma_kernel,
                         cudaFuncAttributeMaxDynamicSharedMemorySize, SM_TOT);

    const int n4x = (B_ * T_ * INF) / 4;
    const int n4w = (OUTF * INF) / 4;
    split_hi_kernel<<<(n4x + 255) / 256, 256>>>(x, xh, n4x);
    split_hilo_kernel<<<(n4w + 255) / 256, 256>>>(w, wh, wl, n4w);

    dim3 grid(OUTF / BN, (B_ * T_) / BM);   // (4, 500)
    gemm_hmma_kernel<<<grid, 256, SM_TOT>>>(xh, wh, wl, cur);
    alif_scan_kernel<<<2 * B_, OUTF>>>(cur, bias, R, beta, beta2, dv, db, out);
}

// round 7
// speedup vs baseline: 2.0485x; 1.4926x over previous
#include <cuda_runtime.h>
#include <cuda_fp16.h>
#include <cstdint>

// Problem constants
#define B_    64
#define T_    1000
#define INF   512
#define OUTF  512

// Scratch (static __device__ allocations are allowed)
__device__ float  g_cur[(size_t)B_ * T_ * OUTF];
__device__ __half g_xh[(size_t)B_ * T_ * INF];
__device__ __half g_wh[(size_t)OUTF * INF];

// ---------------------------------------------------------------------------
// PTX helpers (target-generic: ldmatrix / mma.sync / cp.async only)
// ---------------------------------------------------------------------------
__device__ __forceinline__ uint32_t smem_u32(const void* p) {
    uint32_t a;
    asm("{ .reg .u64 t; cvta.to.shared.u64 t, %1; cvt.u32.u64 %0, t; }"
        : "=r"(a) : "l"(p));
    return a;
}

__device__ __forceinline__ void ldsm_x4(uint32_t* r, uint32_t addr) {
    asm volatile("ldmatrix.sync.aligned.m8n8.x4.shared.b16 {%0,%1,%2,%3}, [%4];"
                 : "=r"(r[0]), "=r"(r[1]), "=r"(r[2]), "=r"(r[3]) : "r"(addr));
}

__device__ __forceinline__ void mma16816(float* d, const uint32_t* a,
                                         const uint32_t* b) {
    asm volatile(
        "mma.sync.aligned.m16n8k16.row.col.f32.f16.f16.f32 "
        "{%0,%1,%2,%3}, {%4,%5,%6,%7}, {%8,%9}, {%0,%1,%2,%3};"
        : "+f"(d[0]), "+f"(d[1]), "+f"(d[2]), "+f"(d[3])
        : "r"(a[0]), "r"(a[1]), "r"(a[2]), "r"(a[3]), "r"(b[0]), "r"(b[1]));
}

#define CP_ASYNC16(dst, src)                                                  \
    asm volatile("cp.async.cg.shared.global [%0], [%1], 16;" :: "r"(dst), "l"(src))
#define CP_COMMIT() asm volatile("cp.async.commit_group;" ::: "memory")
#define CP_WAIT2()  asm volatile("cp.async.wait_group 2;" ::: "memory")

// ---------------------------------------------------------------------------
// Stage 0: fp32 -> fp16 (round-to-nearest)
// ---------------------------------------------------------------------------
__global__ void split_hi_kernel(const float* __restrict__ src,
                                __half* __restrict__ hi, int n4)
{
    int i = blockIdx.x * blockDim.x + threadIdx.x;
    if (i >= n4) return;
    float4 v = ((const float4*)src)[i];
    __half h0 = __float2half_rn(v.x);
    __half h1 = __float2half_rn(v.y);
    __half h2 = __float2half_rn(v.z);
    __half h3 = __float2half_rn(v.w);
    uint2 hv;
    hv.x = (uint32_t)__half_as_ushort(h0) | ((uint32_t)__half_as_ushort(h1) << 16);
    hv.y = (uint32_t)__half_as_ushort(h2) | ((uint32_t)__half_as_ushort(h3) << 16);
    ((uint2*)hi)[i] = hv;
}

// Zero-fill (float4)
__global__ void fill_zero_kernel(float* __restrict__ dst, int n4)
{
    int i = blockIdx.x * blockDim.x + threadIdx.x;
    if (i >= n4) return;
    ((float4*)dst)[i] = make_float4(0.f, 0.f, 0.f, 0.f);
}

// ---------------------------------------------------------------------------
// Stage 1: HMMA fp16 single-pass GEMM.  C = xh * wh^T
// BM=128 BN=128 BK=32, 256 thr, 4-stage cp.async, padded 80B rows, 2 CTA/SM.
// ---------------------------------------------------------------------------
#define BM 128
#define BN 128
#define BK 32
#define NSTAGE 4
#define ROWB 80
#define STAGE_BYTES (2 * BM * ROWB)   // A, B: 20480
#define OFF_A  0
#define OFF_B  (BM * ROWB)
#define SM_TOT (NSTAGE * STAGE_BYTES) // 81920

__global__ __launch_bounds__(256, 2) void gemm_hmma_kernel(
    const __half* __restrict__ xh, const __half* __restrict__ wh,
    float* __restrict__ C)
{
    extern __shared__ char smem[];
    const uint32_t sb = smem_u32(smem);
    const int tid  = threadIdx.x;
    const int wid  = tid >> 5;
    const int lane = tid & 31;
    const int bm = blockIdx.y * BM;
    const int bn = blockIdx.x * BN;
    const int wm = (wid >> 2) * 64;
    const int wn = (wid & 3) * 32;

    const int r0 = tid >> 2;
    const int c0 = tid & 3;
    const int r1 = (tid + 256) >> 2;

    float acc[4][4][4];
#pragma unroll
    for (int i = 0; i < 4; ++i)
#pragma unroll
        for (int j = 0; j < 4; ++j)
#pragma unroll
            for (int k = 0; k < 4; ++k) acc[i][j][k] = 0.f;

    const int a_row = (lane & 15);
    const int a_cb  = (lane >> 4) * 16;
    const int b_g   = lane >> 3;
    const int b_row = ((b_g & 2) ? 8 : 0) + (lane & 7);
    const int b_cb  = (b_g & 1) * 16;

#define LOAD_STAGE(st, kt)                                                    \
    do {                                                                      \
        const int koff = (kt) * BK;                                           \
        uint32_t base = sb + (st) * STAGE_BYTES;                              \
        CP_ASYNC16(base + OFF_A + r0 * ROWB + c0 * 16,                        \
                   xh + (size_t)(bm + r0) * INF + koff + c0 * 8);             \
        CP_ASYNC16(base + OFF_A + r1 * ROWB + c0 * 16,                        \
                   xh + (size_t)(bm + r1) * INF + koff + c0 * 8);             \
        CP_ASYNC16(base + OFF_B + r0 * ROWB + c0 * 16,                        \
                   wh + (size_t)(bn + r0) * INF + koff + c0 * 8);             \
        CP_ASYNC16(base + OFF_B + r1 * ROWB + c0 * 16,                        \
                   wh + (size_t)(bn + r1) * INF + koff + c0 * 8);             \
    } while (0)

    LOAD_STAGE(0, 0);
    CP_COMMIT();
    LOAD_STAGE(1, 1);
    CP_COMMIT();
    LOAD_STAGE(2, 2);
    CP_COMMIT();

    const int KT = INF / BK;   // 16
    for (int kt = 0; kt < KT; ++kt) {
        const int st = kt & (NSTAGE - 1);
        CP_WAIT2();
        __syncthreads();

        if (kt + 3 < KT) LOAD_STAGE((kt + 3) & (NSTAGE - 1), kt + 3);
        CP_COMMIT();

        const uint32_t base = sb + st * STAGE_BYTES;
#pragma unroll
        for (int ks = 0; ks < 2; ++ks) {
            uint32_t ah[4][4], bh[4][2];
#pragma unroll
            for (int mi = 0; mi < 4; ++mi) {
                uint32_t ra = base + OFF_A +
                              (uint32_t)(wm + mi * 16 + a_row) * ROWB +
                              ks * 32 + a_cb;
                ldsm_x4(ah[mi], ra);
            }
#pragma unroll
            for (int nj = 0; nj < 2; ++nj) {
                uint32_t rb = base + OFF_B +
                              (uint32_t)(wn + nj * 16 + b_row) * ROWB +
                              ks * 32 + b_cb;
                uint32_t t[4];
                ldsm_x4(t, rb);
                bh[2 * nj][0] = t[0]; bh[2 * nj][1] = t[1];
                bh[2 * nj + 1][0] = t[2]; bh[2 * nj + 1][1] = t[3];
            }
#pragma unroll
            for (int mi = 0; mi < 4; ++mi)
#pragma unroll
                for (int ni = 0; ni < 4; ++ni)
                    mma16816(acc[mi][ni], ah[mi], bh[ni]);
        }
    }

    const int er = lane >> 2;
    const int ec = (lane & 3) * 2;
#pragma unroll
    for (int mi = 0; mi < 4; ++mi) {
#pragma unroll
        for (int ni = 0; ni < 4; ++ni) {
            size_t row0 = (size_t)(bm + wm + mi * 16 + er);
            size_t col  = (size_t)(bn + wn + ni * 8 + ec);
            float2 v0 = make_float2(acc[mi][ni][0], acc[mi][ni][1]);
            float2 v1 = make_float2(acc[mi][ni][2], acc[mi][ni][3]);
            *(float2*)&C[row0 * OUTF + col]       = v0;
            *(float2*)&C[(row0 + 8) * OUTF + col] = v1;
        }
    }
}

// ---------------------------------------------------------------------------
// Stage 2: speculative windowed ALIF scan.  2 CTAs per batch:
// role 0 writes v_full (+zs on spikes), role 1 writes b_full (+z_full on
// spikes). z streams are pre-zero-filled; scan writes z only when nonzero.
// ---------------------------------------------------------------------------
__global__ __launch_bounds__(512, 1) void alif_scan_kernel(
    const float* __restrict__ cur_in,
    const float* __restrict__ bias,
    const float* __restrict__ R,
    const float* __restrict__ beta,
    const float* __restrict__ beta2,
    const float* __restrict__ decay_v,
    const float* __restrict__ decay_b,
    float* __restrict__ out)
{
    const int b    = blockIdx.x >> 1;
    const int role = blockIdx.x & 1;
    const int o    = threadIdx.x;

    __shared__ float zsm[OUTF];

    const float Bias  = bias[o];
    const float Beta  = beta[o];
    const float Beta2 = beta2[o];
    const float Dv    = decay_v[o];
    const float Db    = decay_b[o];
    const float omDv  = 1.f - Dv;
    const float omDb  = 1.f - Db;

    float v = 0.f, z = 0.f, ba = 0.f;

    const size_t SB = (size_t)B_ * T_ * OUTF;
    float* s_zs = out + ((size_t)b * T_) * OUTF + o;
    float* s_v  = out + SB + (((size_t)0 * B_ + b) * (T_ + 1) + 1) * OUTF + o;
    float* s_zf = out + SB + (((size_t)1 * B_ + b) * (T_ + 1) + 1) * OUTF + o;
    float* s_b  = out + SB + (((size_t)2 * B_ + b) * (T_ + 1) + 1) * OUTF + o;

    // t=0 pads of v_full / b_full (z pads handled by fill kernel)
    if (role == 0)
        out[SB + (((size_t)0 * B_ + b) * (T_ + 1)) * OUTF + o] = 0.f;
    else
        out[SB + (((size_t)2 * B_ + b) * (T_ + 1)) * OUTF + o] = 0.f;

    const float* cin = cur_in + ((size_t)b * T_) * OUTF + o;

    float p[8];
#pragma unroll
    for (int j = 0; j < 8; ++j) p[j] = cin[(size_t)j * OUTF];

    for (int t = 0; t < T_; t += 8) {
        float n[8];
        if (t + 8 < T_) {
#pragma unroll
            for (int j = 0; j < 8; ++j) n[j] = cin[(size_t)(t + 8 + j) * OUTF];
        } else {
#pragma unroll
            for (int j = 0; j < 8; ++j) n[j] = 0.f;
        }

        // entry-spike check (feeds rec at step 0 of the window)
        zsm[o] = z;
        int cnt = __syncthreads_count(z != 0.f);
        float rec0 = 0.f;
        if (cnt) {
            for (int jj = 0; jj < OUTF; ++jj)
                if (zsm[jj] != 0.f) rec0 += R[(size_t)o * OUTF + jj];
        }

        // speculative run (rec = 0 for steps 1..7), store v/b immediately
        float sv = v, sz = z, sb2 = ba;
        float oz[8];
        bool any = false;
#pragma unroll
        for (int j = 0; j < 8; ++j) {
            float rec = (j == 0) ? rec0 : 0.f;
            v *= (1.f - z);
            float c = p[j] + Bias + rec;
            v = Dv * v + omDv * (c - ba);
            z = (v >= 1.0f) ? 1.f : 0.f;
            ba = Db * ba + omDb * (Beta * v + Beta2 * z);
            oz[j] = z;
            if (role == 0) s_v[(size_t)(t + j) * OUTF] = v;
            else           s_b[(size_t)(t + j) * OUTF] = ba;
            if (j < 7) any |= (z != 0.f);
        }
        int cnt2 = __syncthreads_count(any);
        if (cnt2) {
            // rollback + exact per-step redo (re-stores overwrite)
            v = sv; z = sz; ba = sb2;
            for (int j = 0; j < 8; ++j) {
                zsm[o] = z;
                int c3 = __syncthreads_count(z != 0.f);
                float rec = 0.f;
                if (c3) {
                    for (int jj = 0; jj < OUTF; ++jj)
                        if (zsm[jj] != 0.f) rec += R[(size_t)o * OUTF + jj];
                }
                v *= (1.f - z);
                float c = p[j] + Bias + rec;
                v = Dv * v + omDv * (c - ba);
                z = (v >= 1.0f) ? 1.f : 0.f;
                ba = Db * ba + omDb * (Beta * v + Beta2 * z);
                oz[j] = z;
                if (role == 0) s_v[(size_t)(t + j) * OUTF] = v;
                else           s_b[(size_t)(t + j) * OUTF] = ba;
                __syncthreads();
            }
        }

        // spike z-writes (zeros already pre-filled)
        bool myspike = false;
#pragma unroll
        for (int j = 0; j < 8; ++j) myspike |= (oz[j] != 0.f);
        if (myspike) {
#pragma unroll
            for (int j = 0; j < 8; ++j) {
                if (oz[j] != 0.f) {
                    if (role == 0) s_zs[(size_t)(t + j) * OUTF] = oz[j];
                    else           s_zf[(size_t)(t + j) * OUTF] = oz[j];
                }
            }
        }

#pragma unroll
        for (int j = 0; j < 8; ++j) p[j] = n[j];
    }
}

// ---------------------------------------------------------------------------
// Launch
// ---------------------------------------------------------------------------
extern "C" void kernel_launch(void* const* d_in, const int* in_sizes, int n_in,
                              void* d_out, int out_size)
{
    const float* x     = (const float*)d_in[0];
    const float* w     = (const float*)d_in[1];
    const float* bias  = (const float*)d_in[2];
    const float* R     = (const float*)d_in[3];
    const float* beta  = (const float*)d_in[4];
    const float* beta2 = (const float*)d_in[5];
    const float* dv    = (const float*)d_in[6];
    const float* db    = (const float*)d_in[7];
    float* out = (float*)d_out;

    float* cur = nullptr;
    __half *xh, *wh;
    cudaGetSymbolAddress((void**)&cur, g_cur);
    cudaGetSymbolAddress((void**)&xh, g_xh);
    cudaGetSymbolAddress((void**)&wh, g_wh);

    cudaFuncSetAttribute(gemm_hmma_kernel,
                         cudaFuncAttributeMaxDynamicSharedMemorySize, SM_TOT);

    const int n4x = (B_ * T_ * INF) / 4;
    const int n4w = (OUTF * INF) / 4;
    split_hi_kernel<<<(n4x + 255) / 256, 256>>>(x, xh, n4x);
    split_hi_kernel<<<(n4w + 255) / 256, 256>>>(w, wh, n4w);

    // zero-fill the z output streams (zs and z_full, incl. z_full t=0 pad)
    const size_t SB = (size_t)B_ * T_ * OUTF;
    const int n4_zs = (int)(SB / 4);                               // zs
    const int n4_zf = (B_ * (T_ + 1) * OUTF) / 4;                  // z_full
    float* zf_base = out + SB + (size_t)1 * B_ * (T_ + 1) * OUTF;
    fill_zero_kernel<<<(n4_zs + 255) / 256, 256>>>(out, n4_zs);
    fill_zero_kernel<<<(n4_zf + 255) / 256, 256>>>(zf_base, n4_zf);

    dim3 grid(OUTF / BN, (B_ * T_) / BM);   // (4, 500)
    gemm_hmma_kernel<<<grid, 256, SM_TOT>>>(xh, wh, cur);
    alif_scan_kernel<<<2 * B_, OUTF>>>(cur, bias, R, beta, beta2, dv, db, out);
}

// round 14
// speedup vs baseline: 2.2145x; 1.0810x over previous
#include <cuda_runtime.h>
#include <cuda_fp16.h>
#include <cstdint>

// Problem constants
#define B_    64
#define T_    1000
#define INF   512
#define OUTF  512

// Scratch (static __device__ allocations are allowed)
__device__ __half g_curh[(size_t)B_ * T_ * OUTF];   // GEMM output, fp16
__device__ __half g_wh[(size_t)OUTF * INF];         // W in fp16

// ---------------------------------------------------------------------------
// PTX helpers (target-generic: ldmatrix / mma.sync / cp.async only)
// ---------------------------------------------------------------------------
__device__ __forceinline__ uint32_t smem_u32(const void* p) {
    uint32_t a;
    asm("{ .reg .u64 t; cvta.to.shared.u64 t, %1; cvt.u32.u64 %0, t; }"
        : "=r"(a) : "l"(p));
    return a;
}

__device__ __forceinline__ void ldsm_x4(uint32_t* r, uint32_t addr) {
    asm volatile("ldmatrix.sync.aligned.m8n8.x4.shared.b16 {%0,%1,%2,%3}, [%4];"
                 : "=r"(r[0]), "=r"(r[1]), "=r"(r[2]), "=r"(r[3]) : "r"(addr));
}

__device__ __forceinline__ void mma16816(float* d, const uint32_t* a,
                                         const uint32_t* b) {
    asm volatile(
        "mma.sync.aligned.m16n8k16.row.col.f32.f16.f16.f32 "
        "{%0,%1,%2,%3}, {%4,%5,%6,%7}, {%8,%9}, {%0,%1,%2,%3};"
        : "+f"(d[0]), "+f"(d[1]), "+f"(d[2]), "+f"(d[3])
        : "r"(a[0]), "r"(a[1]), "r"(a[2]), "r"(a[3]), "r"(b[0]), "r"(b[1]));
}

#define CP_ASYNC16(dst, src)                                                  \
    asm volatile("cp.async.cg.shared.global [%0], [%1], 16;" :: "r"(dst), "l"(src))
#define CP_COMMIT() asm volatile("cp.async.commit_group;" ::: "memory")
#define CP_WAIT2()  asm volatile("cp.async.wait_group 2;" ::: "memory")

// ---------------------------------------------------------------------------
// W fp32 -> fp16 (tiny: 1 MB)
// ---------------------------------------------------------------------------
__global__ void split_hi_kernel(const float* __restrict__ src,
                                __half* __restrict__ hi, int n4)
{
    int i = blockIdx.x * blockDim.x + threadIdx.x;
    if (i >= n4) return;
    float4 v = ((const float4*)src)[i];
    __half h0 = __float2half_rn(v.x);
    __half h1 = __float2half_rn(v.y);
    __half h2 = __float2half_rn(v.z);
    __half h3 = __float2half_rn(v.w);
    uint2 hv;
    hv.x = (uint32_t)__half_as_ushort(h0) | ((uint32_t)__half_as_ushort(h1) << 16);
    hv.y = (uint32_t)__half_as_ushort(h2) | ((uint32_t)__half_as_ushort(h3) << 16);
    ((uint2*)hi)[i] = hv;
}

// Zero-fill two disjoint ranges in one launch
__global__ void fill_zero2_kernel(float* __restrict__ a, int n4a,
                                  float* __restrict__ b, int n4b)
{
    int i = blockIdx.x * blockDim.x + threadIdx.x;
    if (i < n4a)
        ((float4*)a)[i] = make_float4(0.f, 0.f, 0.f, 0.f);
    else if (i < n4a + n4b)
        ((float4*)b)[i - n4a] = make_float4(0.f, 0.f, 0.f, 0.f);
}

// ---------------------------------------------------------------------------
// Stage 1: HMMA fp16 GEMM with fused A conversion.  C = fp16(x) * wh^T (fp16 out)
// BM=128 BN=128 BK=32, 256 thr.  A: LDG fp32 -> cvt -> STS (2-stage),
// W: 4-stage cp.async.  C stored as half2.
// ---------------------------------------------------------------------------
#define BM 128
#define BN 128
#define BK 32
#define WSTAGE 4
#define ROWB 80                          // 64B data + 16B pad per fp16 row
#define TILEB (BM * ROWB)                // 10240 per fp16 tile
#define OFF_A  0                         // A: 2 stages
#define OFF_W  (2 * TILEB)               // W: 4 stages
#define SM_TOT (OFF_W + WSTAGE * TILEB)  // 61440

__global__ __launch_bounds__(256, 2) void gemm_hmma_kernel(
    const float* __restrict__ X, const __half* __restrict__ wh,
    __half* __restrict__ C)
{
    extern __shared__ char smem[];
    const uint32_t sb = smem_u32(smem);
    const int tid  = threadIdx.x;
    const int wid  = tid >> 5;
    const int lane = tid & 31;
    const int bm = blockIdx.y * BM;
    const int bn = blockIdx.x * BN;
    const int wm = (wid >> 2) * 64;
    const int wn = (wid & 3) * 32;

    const int r0 = tid >> 2;
    const int c0 = tid & 3;
    const int r1 = (tid + 256) >> 2;

    float4 areg[4];

    float acc[4][4][4];
#pragma unroll
    for (int i = 0; i < 4; ++i)
#pragma unroll
        for (int j = 0; j < 4; ++j)
#pragma unroll
            for (int k = 0; k < 4; ++k) acc[i][j][k] = 0.f;

    const int a_row = (lane & 15);
    const int a_cb  = (lane >> 4) * 16;
    const int b_g   = lane >> 3;
    const int b_row = ((b_g & 2) ? 8 : 0) + (lane & 7);
    const int b_cb  = (b_g & 1) * 16;

#define LOAD_W(st, kt)                                                        \
    do {                                                                      \
        const int koff = (kt) * BK;                                           \
        uint32_t base = sb + OFF_W + (st) * TILEB;                            \
        CP_ASYNC16(base + r0 * ROWB + c0 * 16,                                \
                   wh + (size_t)(bn + r0) * INF + koff + c0 * 8);             \
        CP_ASYNC16(base + r1 * ROWB + c0 * 16,                                \
                   wh + (size_t)(bn + r1) * INF + koff + c0 * 8);             \
    } while (0)

#define LDG_A(kt)                                                             \
    do {                                                                      \
        const int koff = (kt) * BK;                                           \
        _Pragma("unroll")                                                     \
        for (int s = 0; s < 4; ++s) {                                         \
            int idx = tid + s * 256;                                          \
            int row = idx >> 3;                                               \
            int c4  = idx & 7;                                                \
            areg[s] = *(const float4*)&X[(size_t)(bm + row) * INF + koff + c4 * 4]; \
        }                                                                     \
    } while (0)

#define STS_A(buf)                                                            \
    do {                                                                      \
        _Pragma("unroll")                                                     \
        for (int s = 0; s < 4; ++s) {                                         \
            int idx = tid + s * 256;                                          \
            int row = idx >> 3;                                               \
            int c4  = idx & 7;                                                \
            float4 v = areg[s];                                               \
            uint2 hv;                                                         \
            hv.x = (uint32_t)__half_as_ushort(__float2half_rn(v.x)) |         \
                   ((uint32_t)__half_as_ushort(__float2half_rn(v.y)) << 16);  \
            hv.y = (uint32_t)__half_as_ushort(__float2half_rn(v.z)) |         \
                   ((uint32_t)__half_as_ushort(__float2half_rn(v.w)) << 16);  \
            *(uint2*)(smem + OFF_A + (buf) * TILEB + row * ROWB + c4 * 8) = hv; \
        }                                                                     \
    } while (0)

    // prologue
    LOAD_W(0, 0); CP_COMMIT();
    LOAD_W(1, 1); CP_COMMIT();
    LOAD_W(2, 2); CP_COMMIT();
    LDG_A(0);

    const int KT = INF / BK;   // 16
    for (int kt = 0; kt < KT; ++kt) {
        const int wst = kt & (WSTAGE - 1);
        const int ab  = kt & 1;

        CP_WAIT2();
        __syncthreads();          // prev compute done reading A buf `ab`
        STS_A(ab);                // fill A buf for this kt
        __syncthreads();          // A visible to all warps

        if (kt + 1 < KT) LDG_A(kt + 1);                            // next A
        if (kt + 3 < KT) LOAD_W((kt + 3) & (WSTAGE - 1), kt + 3);  // W prefetch
        CP_COMMIT();

        const uint32_t abase = sb + OFF_A + ab * TILEB;
        const uint32_t wbase = sb + OFF_W + wst * TILEB;
#pragma unroll
        for (int ks = 0; ks < 2; ++ks) {
            uint32_t ah[4][4], bh[4][2];
#pragma unroll
            for (int mi = 0; mi < 4; ++mi) {
                uint32_t ra = abase +
                              (uint32_t)(wm + mi * 16 + a_row) * ROWB +
                              ks * 32 + a_cb;
                ldsm_x4(ah[mi], ra);
            }
#pragma unroll
            for (int nj = 0; nj < 2; ++nj) {
                uint32_t rb = wbase +
                              (uint32_t)(wn + nj * 16 + b_row) * ROWB +
                              ks * 32 + b_cb;
                uint32_t t[4];
                ldsm_x4(t, rb);
                bh[2 * nj][0] = t[0]; bh[2 * nj][1] = t[1];
                bh[2 * nj + 1][0] = t[2]; bh[2 * nj + 1][1] = t[3];
            }
#pragma unroll
            for (int mi = 0; mi < 4; ++mi)
#pragma unroll
                for (int ni = 0; ni < 4; ++ni)
                    mma16816(acc[mi][ni], ah[mi], bh[ni]);
        }
    }

    // epilogue: fp16 half2 stores
    const int er = lane >> 2;
    const int ec = (lane & 3) * 2;
#pragma unroll
    for (int mi = 0; mi < 4; ++mi) {
#pragma unroll
        for (int ni = 0; ni < 4; ++ni) {
            size_t row0 = (size_t)(bm + wm + mi * 16 + er);
            size_t col  = (size_t)(bn + wn + ni * 8 + ec);
            __half2 v0 = __floats2half2_rn(acc[mi][ni][0], acc[mi][ni][1]);
            __half2 v1 = __floats2half2_rn(acc[mi][ni][2], acc[mi][ni][3]);
            *(__half2*)&C[row0 * OUTF + col]       = v0;
            *(__half2*)&C[(row0 + 8) * OUTF + col] = v1;
        }
    }
}

// ---------------------------------------------------------------------------
// Stage 2: speculative windowed ALIF scan (WIN=8: divides T=1000 exactly).
// fp16 cur input.  2 CTAs per batch: role 0 -> v_full (+zs spikes),
// role 1 -> b_full (+z_full spikes).  z streams pre-zero-filled.
// ---------------------------------------------------------------------------
#define WIN 8

__global__ __launch_bounds__(512, 1) void alif_scan_kernel(
    const __half* __restrict__ cur_in,
    const float* __restrict__ bias,
    const float* __restrict__ R,
    const float* __restrict__ beta,
    const float* __restrict__ beta2,
    const float* __restrict__ decay_v,
    const float* __restrict__ decay_b,
    float* __restrict__ out)
{
    const int b    = blockIdx.x >> 1;
    const int role = blockIdx.x & 1;
    const int o    = threadIdx.x;

    __shared__ float zsm[OUTF];

    const float Bias  = bias[o];
    const float Beta  = beta[o];
    const float Beta2 = beta2[o];
    const float Dv    = decay_v[o];
    const float Db    = decay_b[o];
    const float omDv  = 1.f - Dv;
    const float omDb  = 1.f - Db;

    float v = 0.f, z = 0.f, ba = 0.f;

    const size_t SB = (size_t)B_ * T_ * OUTF;
    float* s_zs = out + ((size_t)b * T_) * OUTF + o;
    float* s_v  = out + SB + (((size_t)0 * B_ + b) * (T_ + 1) + 1) * OUTF + o;
    float* s_zf = out + SB + (((size_t)1 * B_ + b) * (T_ + 1) + 1) * OUTF + o;
    float* s_b  = out + SB + (((size_t)2 * B_ + b) * (T_ + 1) + 1) * OUTF + o;

    if (role == 0)
        out[SB + (((size_t)0 * B_ + b) * (T_ + 1)) * OUTF + o] = 0.f;
    else
        out[SB + (((size_t)2 * B_ + b) * (T_ + 1)) * OUTF + o] = 0.f;

    const __half* cin = cur_in + ((size_t)b * T_) * OUTF + o;

    float p[WIN];
#pragma unroll
    for (int j = 0; j < WIN; ++j) p[j] = __half2float(cin[(size_t)j * OUTF]);

    for (int t = 0; t < T_; t += WIN) {
        float n[WIN];
        if (t + WIN < T_) {
#pragma unroll
            for (int j = 0; j < WIN; ++j)
                n[j] = __half2float(cin[(size_t)(t + WIN + j) * OUTF]);
        } else {
#pragma unroll
            for (int j = 0; j < WIN; ++j) n[j] = 0.f;
        }

        // entry-spike check (feeds rec at step 0 of the window)
        zsm[o] = z;
        int cnt = __syncthreads_count(z != 0.f);
        float rec0 = 0.f;
        if (cnt) {
            for (int jj = 0; jj < OUTF; ++jj)
                if (zsm[jj] != 0.f) rec0 += R[(size_t)o * OUTF + jj];
        }

        // speculative run (rec = 0 for steps 1..WIN-1); spike mask in bits
        float sv = v, sz = z, sb2 = ba;
        uint32_t zmask = 0;
#pragma unroll
        for (int j = 0; j < WIN; ++j) {
            float rec = (j == 0) ? rec0 : 0.f;
            v *= (1.f - z);
            float c = p[j] + Bias + rec;
            v = Dv * v + omDv * (c - ba);
            z = (v >= 1.0f) ? 1.f : 0.f;
            ba = Db * ba + omDb * (Beta * v + Beta2 * z);
            if (z != 0.f) zmask |= (1u << j);
            if (role == 0) s_v[(size_t)(t + j) * OUTF] = v;
            else           s_b[(size_t)(t + j) * OUTF] = ba;
        }
        int cnt2 = __syncthreads_count((zmask & ((1u << (WIN - 1)) - 1u)) != 0u);
        if (cnt2) {
            // rollback + exact per-step redo (re-stores overwrite)
            v = sv; z = sz; ba = sb2;
            zmask = 0;
            for (int j = 0; j < WIN; ++j) {
                zsm[o] = z;
                int c3 = __syncthreads_count(z != 0.f);
                float rec = 0.f;
                if (c3) {
                    for (int jj = 0; jj < OUTF; ++jj)
                        if (zsm[jj] != 0.f) rec += R[(size_t)o * OUTF + jj];
                }
                v *= (1.f - z);
                float c = p[j] + Bias + rec;
                v = Dv * v + omDv * (c - ba);
                z = (v >= 1.0f) ? 1.f : 0.f;
                ba = Db * ba + omDb * (Beta * v + Beta2 * z);
                if (z != 0.f) zmask |= (1u << j);
                if (role == 0) s_v[(size_t)(t + j) * OUTF] = v;
                else           s_b[(size_t)(t + j) * OUTF] = ba;
                __syncthreads();
            }
        }

        // spike z-writes (zeros pre-filled)
        if (zmask) {
#pragma unroll
            for (int j = 0; j < WIN; ++j) {
                if (zmask & (1u << j)) {
                    if (role == 0) s_zs[(size_t)(t + j) * OUTF] = 1.0f;
                    else           s_zf[(size_t)(t + j) * OUTF] = 1.0f;
                }
            }
        }

#pragma unroll
        for (int j = 0; j < WIN; ++j) p[j] = n[j];
    }
}

// ---------------------------------------------------------------------------
// Launch
// ---------------------------------------------------------------------------
extern "C" void kernel_launch(void* const* d_in, const int* in_sizes, int n_in,
                              void* d_out, int out_size)
{
    const float* x     = (const float*)d_in[0];
    const float* w     = (const float*)d_in[1];
    const float* bias  = (const float*)d_in[2];
    const float* R     = (const float*)d_in[3];
    const float* beta  = (const float*)d_in[4];
    const float* beta2 = (const float*)d_in[5];
    const float* dv    = (const float*)d_in[6];
    const float* db    = (const float*)d_in[7];
    float* out = (float*)d_out;

    __half *curh, *wh;
    cudaGetSymbolAddress((void**)&curh, g_curh);
    cudaGetSymbolAddress((void**)&wh, g_wh);

    cudaFuncSetAttribute(gemm_hmma_kernel,
                         cudaFuncAttributeMaxDynamicSharedMemorySize, SM_TOT);

    const int n4w = (OUTF * INF) / 4;
    split_hi_kernel<<<(n4w + 255) / 256, 256>>>(w, wh, n4w);

    // zero-fill z output streams (zs, z_full incl. its t=0 pad) in one launch
    const size_t SB = (size_t)B_ * T_ * OUTF;
    const int n4_zs = (int)(SB / 4);
    const int n4_zf = (B_ * (T_ + 1) * OUTF) / 4;
    float* zf_base = out + SB + (size_t)1 * B_ * (T_ + 1) * OUTF;
    fill_zero2_kernel<<<(n4_zs + n4_zf + 255) / 256, 256>>>(out, n4_zs,
                                                            zf_base, n4_zf);

    dim3 grid(OUTF / BN, (B_ * T_) / BM);   // (4, 500)
    gemm_hmma_kernel<<<grid, 256, SM_TOT>>>(x, wh, curh);
    alif_scan_kernel<<<2 * B_, OUTF>>>(curh, bias, R, beta, beta2, dv, db, out);
}